// round 4
// baseline (speedup 1.0000x reference)
#include <cuda_runtime.h>
#include <cstdint>

#define NN   100000
#define EMAX 1600000
#define F    16

// ---------------- scratch (static __device__, no allocs) ----------------
__device__ int g_deg[NN];
__device__ int g_cur[NN];
__device__ int g_off[NN + 1];
__device__ int g_dst[EMAX];
__device__ __align__(16) float g_eas[(size_t)EMAX * 8];  // sorted edge_attr
__device__ __align__(16) float g_h1[NN * F];
__device__ __align__(16) float g_h2[NN * F];
__device__ int g_idx64;

// ---------------- weights in constant memory ----------------
__constant__ float c1w1[16 * F];
__constant__ float c1b1[F];
__constant__ float c1w2[F * F];
__constant__ float c1b2[F];
__constant__ float c2w1[40 * F];
__constant__ float c2b1[F];
__constant__ float c2w2[F * F];
__constant__ float c2b2[F];
__constant__ float clw1[F * F];
__constant__ float clb1[F];
__constant__ float clw2[F];
__constant__ float clb2[1];

// ---------------- preprocessing ----------------
__global__ void detect_kernel(const void* ei, int N) {
    const long long* p64 = (const long long*)ei;
    bool ok = true;
#pragma unroll
    for (int k = 0; k < 4; k++) {
        long long v = p64[k];
        if (v < 0 || v >= N) ok = false;
    }
    g_idx64 = ok ? 1 : 0;
}

__global__ void zero_deg_kernel(int n) {
    int i = blockIdx.x * blockDim.x + threadIdx.x;
    if (i < n) g_deg[i] = 0;
}

__global__ void hist_kernel(const void* __restrict__ ei, int E) {
    int e = blockIdx.x * blockDim.x + threadIdx.x;
    if (e >= E) return;
    int s = g_idx64 ? (int)((const long long*)ei)[e] : ((const int*)ei)[e];
    atomicAdd(&g_deg[s], 1);
}

// single-block exclusive scan of g_deg -> g_off (and g_cur as write cursor)
__global__ void scan_kernel(int n) {
    __shared__ int sdata[1024];
    __shared__ int carry;
    int tid = threadIdx.x;
    if (tid == 0) carry = 0;
    __syncthreads();
    for (int base = 0; base < n; base += 1024) {
        int i = base + tid;
        int v = (i < n) ? g_deg[i] : 0;
        sdata[tid] = v;
        __syncthreads();
        for (int off = 1; off < 1024; off <<= 1) {
            int t = (tid >= off) ? sdata[tid - off] : 0;
            __syncthreads();
            sdata[tid] += t;
            __syncthreads();
        }
        int excl = carry + sdata[tid] - v;
        if (i < n) { g_off[i] = excl; g_cur[i] = excl; }
        int total = sdata[1023];
        __syncthreads();
        if (tid == 0) carry += total;
        __syncthreads();
    }
    if (tid == 0) g_off[n] = carry;
}

__global__ void scatter_kernel(const void* __restrict__ ei,
                               const float* __restrict__ ea, int E) {
    int e = blockIdx.x * blockDim.x + threadIdx.x;
    if (e >= E) return;
    int s, d;
    if (g_idx64) {
        const long long* p = (const long long*)ei;
        s = (int)p[e]; d = (int)p[(size_t)E + e];
    } else {
        const int* p = (const int*)ei;
        s = p[e]; d = p[(size_t)E + e];
    }
    int pos = atomicAdd(&g_cur[s], 1);
    g_dst[pos] = d;
    float4 a0 = *(const float4*)(ea + (size_t)e * 8);
    float4 a1 = *(const float4*)(ea + (size_t)e * 8 + 4);
    *(float4*)(g_eas + (size_t)pos * 8)     = a0;
    *(float4*)(g_eas + (size_t)pos * 8 + 4) = a1;
}

// ---------------- conv layers: one half-warp (16 lanes) per node ----------------
__global__ void __launch_bounds__(256) conv1_kernel(const float* __restrict__ x, int N) {
    int gid = blockIdx.x * blockDim.x + threadIdx.x;
    int node = gid >> 4;
    int l = gid & 15;
    if (node >= N) return;

    int start = g_off[node];
    int end   = g_off[node + 1];

    float4 xi = *(const float4*)(x + (size_t)node * 4);  // broadcast within group

    float acc[F];
#pragma unroll
    for (int j = 0; j < F; j++) acc[j] = 0.f;

    for (int p = start + l; p < end; p += 16) {
        int d = g_dst[p];
        float4 xj = *(const float4*)(x + (size_t)d * 4);
        float4 a0 = *(const float4*)(g_eas + (size_t)p * 8);
        float4 a1 = *(const float4*)(g_eas + (size_t)p * 8 + 4);

        float in[16] = {xi.x, xi.y, xi.z, xi.w, xj.x, xj.y, xj.z, xj.w,
                        a0.x, a0.y, a0.z, a0.w, a1.x, a1.y, a1.z, a1.w};

        float h[F];
#pragma unroll
        for (int j = 0; j < F; j++) h[j] = c1b1[j];
#pragma unroll
        for (int i = 0; i < 16; i++) {
            float v = in[i];
#pragma unroll
            for (int j = 0; j < F; j++) h[j] = fmaf(v, c1w1[i * F + j], h[j]);
        }
#pragma unroll
        for (int j = 0; j < F; j++) h[j] = fmaxf(h[j], 0.f);

        float o[F];
#pragma unroll
        for (int j = 0; j < F; j++) o[j] = c1b2[j];
#pragma unroll
        for (int i = 0; i < F; i++) {
            float v = h[i];
#pragma unroll
            for (int j = 0; j < F; j++) o[j] = fmaf(v, c1w2[i * F + j], o[j]);
        }
#pragma unroll
        for (int j = 0; j < F; j++) acc[j] = fmaxf(acc[j], o[j]);
    }

    unsigned mask = 0xFFFFu << (threadIdx.x & 16);
#pragma unroll
    for (int w = 8; w >= 1; w >>= 1) {
#pragma unroll
        for (int j = 0; j < F; j++)
            acc[j] = fmaxf(acc[j], __shfl_xor_sync(mask, acc[j], w, 16));
    }
    if (l == 0) {
        float* out = g_h1 + (size_t)node * F;
#pragma unroll
        for (int q = 0; q < 4; q++)
            *(float4*)(out + q * 4) = make_float4(acc[q*4], acc[q*4+1], acc[q*4+2], acc[q*4+3]);
    }
}

__global__ void __launch_bounds__(256) conv2_kernel(int N) {
    int gid = blockIdx.x * blockDim.x + threadIdx.x;
    int node = gid >> 4;
    int l = gid & 15;
    if (node >= N) return;

    int start = g_off[node];
    int end   = g_off[node + 1];

    float hi[F];   // h1[node], broadcast within group
    {
        const float4* ph = (const float4*)(g_h1 + (size_t)node * F);
#pragma unroll
        for (int q = 0; q < 4; q++) {
            float4 v = ph[q];
            hi[q*4+0] = v.x; hi[q*4+1] = v.y; hi[q*4+2] = v.z; hi[q*4+3] = v.w;
        }
    }

    float acc[F];
#pragma unroll
    for (int j = 0; j < F; j++) acc[j] = 0.f;

    for (int p = start + l; p < end; p += 16) {
        int d = g_dst[p];
        float in[40];
#pragma unroll
        for (int i = 0; i < F; i++) in[i] = hi[i];
        {
            const float4* pd = (const float4*)(g_h1 + (size_t)d * F);
#pragma unroll
            for (int q = 0; q < 4; q++) {
                float4 v = pd[q];
                in[16+q*4+0] = v.x; in[16+q*4+1] = v.y; in[16+q*4+2] = v.z; in[16+q*4+3] = v.w;
            }
            float4 a0 = *(const float4*)(g_eas + (size_t)p * 8);
            float4 a1 = *(const float4*)(g_eas + (size_t)p * 8 + 4);
            in[32] = a0.x; in[33] = a0.y; in[34] = a0.z; in[35] = a0.w;
            in[36] = a1.x; in[37] = a1.y; in[38] = a1.z; in[39] = a1.w;
        }

        float h[F];
#pragma unroll
        for (int j = 0; j < F; j++) h[j] = c2b1[j];
#pragma unroll
        for (int i = 0; i < 40; i++) {
            float v = in[i];
#pragma unroll
            for (int j = 0; j < F; j++) h[j] = fmaf(v, c2w1[i * F + j], h[j]);
        }
#pragma unroll
        for (int j = 0; j < F; j++) h[j] = fmaxf(h[j], 0.f);

        float o[F];
#pragma unroll
        for (int j = 0; j < F; j++) o[j] = c2b2[j];
#pragma unroll
        for (int i = 0; i < F; i++) {
            float v = h[i];
#pragma unroll
            for (int j = 0; j < F; j++) o[j] = fmaf(v, c2w2[i * F + j], o[j]);
        }
#pragma unroll
        for (int j = 0; j < F; j++) acc[j] = fmaxf(acc[j], o[j]);
    }

    unsigned mask = 0xFFFFu << (threadIdx.x & 16);
#pragma unroll
    for (int w = 8; w >= 1; w >>= 1) {
#pragma unroll
        for (int j = 0; j < F; j++)
            acc[j] = fmaxf(acc[j], __shfl_xor_sync(mask, acc[j], w, 16));
    }
    if (l == 0) {
        float* out = g_h2 + (size_t)node * F;
#pragma unroll
        for (int q = 0; q < 4; q++)
            *(float4*)(out + q * 4) = make_float4(acc[q*4], acc[q*4+1], acc[q*4+2], acc[q*4+3]);
    }
}

// ---------------- final node MLP ----------------
__global__ void __launch_bounds__(256) node_mlp_kernel(float* __restrict__ out, int n) {
    int i = blockIdx.x * blockDim.x + threadIdx.x;
    if (i >= n) return;

    float in[F];
    const float4* ph = (const float4*)(g_h2 + (size_t)i * F);
#pragma unroll
    for (int q = 0; q < 4; q++) {
        float4 v = ph[q];
        in[q*4+0] = v.x; in[q*4+1] = v.y; in[q*4+2] = v.z; in[q*4+3] = v.w;
    }

    float h[F];
#pragma unroll
    for (int j = 0; j < F; j++) h[j] = clb1[j];
#pragma unroll
    for (int k = 0; k < F; k++) {
        float v = in[k];
#pragma unroll
        for (int j = 0; j < F; j++) h[j] = fmaf(v, clw1[k * F + j], h[j]);
    }
    float acc = clb2[0];
#pragma unroll
    for (int j = 0; j < F; j++) acc += fmaxf(h[j], 0.f) * clw2[j];

    out[i] = acc;
}

// ---------------- launch ----------------
extern "C" void kernel_launch(void* const* d_in, const int* in_sizes, int n_in,
                              void* d_out, int out_size)
{
    const float* x  = (const float*)d_in[0];
    const void*  ei = d_in[1];
    const float* ea = (const float*)d_in[2];

    int N = in_sizes[0] / 4;   // x is [N,4]
    int E = in_sizes[2] / 8;   // edge_attr is [E,8]
    float* out = (float*)d_out;

    // weights -> constant memory (D2D async copies; graph-capturable memcpy nodes)
    cudaMemcpyToSymbolAsync(c1w1, d_in[3],  16 * F * sizeof(float), 0, cudaMemcpyDeviceToDevice);
    cudaMemcpyToSymbolAsync(c1b1, d_in[4],  F * sizeof(float),      0, cudaMemcpyDeviceToDevice);
    cudaMemcpyToSymbolAsync(c1w2, d_in[5],  F * F * sizeof(float),  0, cudaMemcpyDeviceToDevice);
    cudaMemcpyToSymbolAsync(c1b2, d_in[6],  F * sizeof(float),      0, cudaMemcpyDeviceToDevice);
    cudaMemcpyToSymbolAsync(c2w1, d_in[7],  40 * F * sizeof(float), 0, cudaMemcpyDeviceToDevice);
    cudaMemcpyToSymbolAsync(c2b1, d_in[8],  F * sizeof(float),      0, cudaMemcpyDeviceToDevice);
    cudaMemcpyToSymbolAsync(c2w2, d_in[9],  F * F * sizeof(float),  0, cudaMemcpyDeviceToDevice);
    cudaMemcpyToSymbolAsync(c2b2, d_in[10], F * sizeof(float),      0, cudaMemcpyDeviceToDevice);
    cudaMemcpyToSymbolAsync(clw1, d_in[11], F * F * sizeof(float),  0, cudaMemcpyDeviceToDevice);
    cudaMemcpyToSymbolAsync(clb1, d_in[12], F * sizeof(float),      0, cudaMemcpyDeviceToDevice);
    cudaMemcpyToSymbolAsync(clw2, d_in[13], F * sizeof(float),      0, cudaMemcpyDeviceToDevice);
    cudaMemcpyToSymbolAsync(clb2, d_in[14], 1 * sizeof(float),      0, cudaMemcpyDeviceToDevice);

    detect_kernel<<<1, 1>>>(ei, N);
    zero_deg_kernel<<<(N + 255) / 256, 256>>>(N);

    int eblocks = (E + 255) / 256;
    hist_kernel<<<eblocks, 256>>>(ei, E);
    scan_kernel<<<1, 1024>>>(N);
    scatter_kernel<<<eblocks, 256>>>(ei, ea, E);

    int cblocks = ((N * 16) + 255) / 256;
    conv1_kernel<<<cblocks, 256>>>(x, N);
    conv2_kernel<<<cblocks, 256>>>(N);

    node_mlp_kernel<<<(N + 255) / 256, 256>>>(out, N);
}

// round 5
// speedup vs baseline: 1.5318x; 1.5318x over previous
#include <cuda_runtime.h>
#include <cstdint>

#define NN   100000
#define EMAX 1600000
#define F    16

// ---------------- scratch (static __device__, no allocs) ----------------
__device__ int g_deg[NN];
__device__ int g_cur[NN];
__device__ int g_off[NN + 1];
__device__ int g_bsum[128];
__device__ int g_dst[EMAX];
__device__ __align__(16) float g_eas[(size_t)EMAX * 8];  // sorted edge_attr
__device__ __align__(16) float g_h1[NN * F];
__device__ __align__(16) float g_h2[NN * F];
__device__ int g_idx64;

// ---------------- weights in constant memory ----------------
__constant__ float c1w1[16 * F];
__constant__ float c1b1[F];
__constant__ float c1w2[F * F];
__constant__ float c1b2[F];
__constant__ float c2w1[40 * F];
__constant__ float c2b1[F];
__constant__ float c2w2[F * F];
__constant__ float c2b2[F];
__constant__ float clw1[F * F];
__constant__ float clb1[F];
__constant__ float clw2[F];
__constant__ float clb2[1];

// ---------------- preprocessing ----------------
__global__ void detect_kernel(const void* ei, int N) {
    const long long* p64 = (const long long*)ei;
    bool ok = true;
#pragma unroll
    for (int k = 0; k < 4; k++) {
        long long v = p64[k];
        if (v < 0 || v >= N) ok = false;
    }
    g_idx64 = ok ? 1 : 0;
}

__global__ void zero_deg_kernel(int n) {
    int i = blockIdx.x * blockDim.x + threadIdx.x;
    if (i < n) g_deg[i] = 0;
}

__global__ void hist_kernel(const void* __restrict__ ei, int E) {
    int e = blockIdx.x * blockDim.x + threadIdx.x;
    if (e >= E) return;
    int s = g_idx64 ? (int)((const long long*)ei)[e] : ((const int*)ei)[e];
    atomicAdd(&g_deg[s], 1);
}

// --- two-level scan: per-block scan, scan of block sums, add offsets ---
__global__ void __launch_bounds__(1024) scan_blocks_kernel(int n) {
    __shared__ int wsum[32];
    int i = blockIdx.x * 1024 + threadIdx.x;
    int lane = threadIdx.x & 31;
    int wid  = threadIdx.x >> 5;
    int v = (i < n) ? g_deg[i] : 0;
    int s = v;
#pragma unroll
    for (int o = 1; o < 32; o <<= 1) {
        int t = __shfl_up_sync(~0u, s, o);
        if (lane >= o) s += t;
    }
    if (lane == 31) wsum[wid] = s;
    __syncthreads();
    if (wid == 0) {
        int ws = wsum[lane];
#pragma unroll
        for (int o = 1; o < 32; o <<= 1) {
            int t = __shfl_up_sync(~0u, ws, o);
            if (lane >= o) ws += t;
        }
        wsum[lane] = ws;
    }
    __syncthreads();
    int excl = s - v + (wid > 0 ? wsum[wid - 1] : 0);
    if (i < n) g_off[i] = excl;
    if (threadIdx.x == 1023) g_bsum[blockIdx.x] = wsum[31];
}

__global__ void __launch_bounds__(128) scan_tops_kernel(int nb) {
    __shared__ int wsum[4];
    int lane = threadIdx.x & 31;
    int wid  = threadIdx.x >> 5;
    int v = (threadIdx.x < nb) ? g_bsum[threadIdx.x] : 0;
    int s = v;
#pragma unroll
    for (int o = 1; o < 32; o <<= 1) {
        int t = __shfl_up_sync(~0u, s, o);
        if (lane >= o) s += t;
    }
    if (lane == 31) wsum[wid] = s;
    __syncthreads();
    int base = 0;
#pragma unroll
    for (int k = 0; k < 4; k++) if (k < wid) base += wsum[k];
    if (threadIdx.x < nb) g_bsum[threadIdx.x] = base + s - v;
}

__global__ void __launch_bounds__(1024) add_offsets_kernel(int n, int E) {
    int i = blockIdx.x * 1024 + threadIdx.x;
    if (i < n) {
        int o = g_off[i] + g_bsum[blockIdx.x];
        g_off[i] = o;
        g_cur[i] = o;
    }
    if (i == 0) g_off[n] = E;
}

__global__ void scatter_kernel(const void* __restrict__ ei,
                               const float* __restrict__ ea, int E) {
    int e = blockIdx.x * blockDim.x + threadIdx.x;
    if (e >= E) return;
    int s, d;
    if (g_idx64) {
        const long long* p = (const long long*)ei;
        s = (int)p[e]; d = (int)p[(size_t)E + e];
    } else {
        const int* p = (const int*)ei;
        s = p[e]; d = p[(size_t)E + e];
    }
    int pos = atomicAdd(&g_cur[s], 1);
    g_dst[pos] = d;
    float4 a0 = *(const float4*)(ea + (size_t)e * 8);
    float4 a1 = *(const float4*)(ea + (size_t)e * 8 + 4);
    *(float4*)(g_eas + (size_t)pos * 8)     = a0;
    *(float4*)(g_eas + (size_t)pos * 8 + 4) = a1;
}

// ---------------- conv layers: one half-warp (16 lanes) per node ----------------
__global__ void __launch_bounds__(256) conv1_kernel(const float* __restrict__ x, int N) {
    int gid = blockIdx.x * blockDim.x + threadIdx.x;
    int node = gid >> 4;
    int l = gid & 15;
    if (node >= N) return;

    int start = g_off[node];
    int end   = g_off[node + 1];

    float4 xi = *(const float4*)(x + (size_t)node * 4);  // broadcast within group

    float acc[F];
#pragma unroll
    for (int j = 0; j < F; j++) acc[j] = 0.f;

    for (int p = start + l; p < end; p += 16) {
        int d = g_dst[p];
        float4 xj = *(const float4*)(x + (size_t)d * 4);
        float4 a0 = *(const float4*)(g_eas + (size_t)p * 8);
        float4 a1 = *(const float4*)(g_eas + (size_t)p * 8 + 4);

        float in[16] = {xi.x, xi.y, xi.z, xi.w, xj.x, xj.y, xj.z, xj.w,
                        a0.x, a0.y, a0.z, a0.w, a1.x, a1.y, a1.z, a1.w};

        float h[F];
#pragma unroll
        for (int j = 0; j < F; j++) h[j] = c1b1[j];
#pragma unroll
        for (int i = 0; i < 16; i++) {
            float v = in[i];
#pragma unroll
            for (int j = 0; j < F; j++) h[j] = fmaf(v, c1w1[i * F + j], h[j]);
        }
#pragma unroll
        for (int j = 0; j < F; j++) h[j] = fmaxf(h[j], 0.f);

        float o[F];
#pragma unroll
        for (int j = 0; j < F; j++) o[j] = c1b2[j];
#pragma unroll
        for (int i = 0; i < F; i++) {
            float v = h[i];
#pragma unroll
            for (int j = 0; j < F; j++) o[j] = fmaf(v, c1w2[i * F + j], o[j]);
        }
#pragma unroll
        for (int j = 0; j < F; j++) acc[j] = fmaxf(acc[j], o[j]);
    }

    unsigned mask = 0xFFFFu << (threadIdx.x & 16);
#pragma unroll
    for (int w = 8; w >= 1; w >>= 1) {
#pragma unroll
        for (int j = 0; j < F; j++)
            acc[j] = fmaxf(acc[j], __shfl_xor_sync(mask, acc[j], w, 16));
    }
    if (l == 0) {
        float* out = g_h1 + (size_t)node * F;
#pragma unroll
        for (int q = 0; q < 4; q++)
            *(float4*)(out + q * 4) = make_float4(acc[q*4], acc[q*4+1], acc[q*4+2], acc[q*4+3]);
    }
}

__global__ void __launch_bounds__(256) conv2_kernel(int N) {
    int gid = blockIdx.x * blockDim.x + threadIdx.x;
    int node = gid >> 4;
    int l = gid & 15;
    if (node >= N) return;

    int start = g_off[node];
    int end   = g_off[node + 1];

    float hi[F];   // h1[node], broadcast within group
    {
        const float4* ph = (const float4*)(g_h1 + (size_t)node * F);
#pragma unroll
        for (int q = 0; q < 4; q++) {
            float4 v = ph[q];
            hi[q*4+0] = v.x; hi[q*4+1] = v.y; hi[q*4+2] = v.z; hi[q*4+3] = v.w;
        }
    }

    float acc[F];
#pragma unroll
    for (int j = 0; j < F; j++) acc[j] = 0.f;

    for (int p = start + l; p < end; p += 16) {
        int d = g_dst[p];
        float in[40];
#pragma unroll
        for (int i = 0; i < F; i++) in[i] = hi[i];
        {
            const float4* pd = (const float4*)(g_h1 + (size_t)d * F);
#pragma unroll
            for (int q = 0; q < 4; q++) {
                float4 v = pd[q];
                in[16+q*4+0] = v.x; in[16+q*4+1] = v.y; in[16+q*4+2] = v.z; in[16+q*4+3] = v.w;
            }
            float4 a0 = *(const float4*)(g_eas + (size_t)p * 8);
            float4 a1 = *(const float4*)(g_eas + (size_t)p * 8 + 4);
            in[32] = a0.x; in[33] = a0.y; in[34] = a0.z; in[35] = a0.w;
            in[36] = a1.x; in[37] = a1.y; in[38] = a1.z; in[39] = a1.w;
        }

        float h[F];
#pragma unroll
        for (int j = 0; j < F; j++) h[j] = c2b1[j];
#pragma unroll
        for (int i = 0; i < 40; i++) {
            float v = in[i];
#pragma unroll
            for (int j = 0; j < F; j++) h[j] = fmaf(v, c2w1[i * F + j], h[j]);
        }
#pragma unroll
        for (int j = 0; j < F; j++) h[j] = fmaxf(h[j], 0.f);

        float o[F];
#pragma unroll
        for (int j = 0; j < F; j++) o[j] = c2b2[j];
#pragma unroll
        for (int i = 0; i < F; i++) {
            float v = h[i];
#pragma unroll
            for (int j = 0; j < F; j++) o[j] = fmaf(v, c2w2[i * F + j], o[j]);
        }
#pragma unroll
        for (int j = 0; j < F; j++) acc[j] = fmaxf(acc[j], o[j]);
    }

    unsigned mask = 0xFFFFu << (threadIdx.x & 16);
#pragma unroll
    for (int w = 8; w >= 1; w >>= 1) {
#pragma unroll
        for (int j = 0; j < F; j++)
            acc[j] = fmaxf(acc[j], __shfl_xor_sync(mask, acc[j], w, 16));
    }
    if (l == 0) {
        float* out = g_h2 + (size_t)node * F;
#pragma unroll
        for (int q = 0; q < 4; q++)
            *(float4*)(out + q * 4) = make_float4(acc[q*4], acc[q*4+1], acc[q*4+2], acc[q*4+3]);
    }
}

// ---------------- final node MLP ----------------
__global__ void __launch_bounds__(256) node_mlp_kernel(float* __restrict__ out, int n) {
    int i = blockIdx.x * blockDim.x + threadIdx.x;
    if (i >= n) return;

    float in[F];
    const float4* ph = (const float4*)(g_h2 + (size_t)i * F);
#pragma unroll
    for (int q = 0; q < 4; q++) {
        float4 v = ph[q];
        in[q*4+0] = v.x; in[q*4+1] = v.y; in[q*4+2] = v.z; in[q*4+3] = v.w;
    }

    float h[F];
#pragma unroll
    for (int j = 0; j < F; j++) h[j] = clb1[j];
#pragma unroll
    for (int k = 0; k < F; k++) {
        float v = in[k];
#pragma unroll
        for (int j = 0; j < F; j++) h[j] = fmaf(v, clw1[k * F + j], h[j]);
    }
    float acc = clb2[0];
#pragma unroll
    for (int j = 0; j < F; j++) acc += fmaxf(h[j], 0.f) * clw2[j];

    out[i] = acc;
}

// ---------------- launch ----------------
extern "C" void kernel_launch(void* const* d_in, const int* in_sizes, int n_in,
                              void* d_out, int out_size)
{
    const float* x  = (const float*)d_in[0];
    const void*  ei = d_in[1];
    const float* ea = (const float*)d_in[2];

    int N = in_sizes[0] / 4;   // x is [N,4]
    int E = in_sizes[2] / 8;   // edge_attr is [E,8]
    float* out = (float*)d_out;

    // weights -> constant memory (D2D async copies; graph-capturable memcpy nodes)
    cudaMemcpyToSymbolAsync(c1w1, d_in[3],  16 * F * sizeof(float), 0, cudaMemcpyDeviceToDevice);
    cudaMemcpyToSymbolAsync(c1b1, d_in[4],  F * sizeof(float),      0, cudaMemcpyDeviceToDevice);
    cudaMemcpyToSymbolAsync(c1w2, d_in[5],  F * F * sizeof(float),  0, cudaMemcpyDeviceToDevice);
    cudaMemcpyToSymbolAsync(c1b2, d_in[6],  F * sizeof(float),      0, cudaMemcpyDeviceToDevice);
    cudaMemcpyToSymbolAsync(c2w1, d_in[7],  40 * F * sizeof(float), 0, cudaMemcpyDeviceToDevice);
    cudaMemcpyToSymbolAsync(c2b1, d_in[8],  F * sizeof(float),      0, cudaMemcpyDeviceToDevice);
    cudaMemcpyToSymbolAsync(c2w2, d_in[9],  F * F * sizeof(float),  0, cudaMemcpyDeviceToDevice);
    cudaMemcpyToSymbolAsync(c2b2, d_in[10], F * sizeof(float),      0, cudaMemcpyDeviceToDevice);
    cudaMemcpyToSymbolAsync(clw1, d_in[11], F * F * sizeof(float),  0, cudaMemcpyDeviceToDevice);
    cudaMemcpyToSymbolAsync(clb1, d_in[12], F * sizeof(float),      0, cudaMemcpyDeviceToDevice);
    cudaMemcpyToSymbolAsync(clw2, d_in[13], F * sizeof(float),      0, cudaMemcpyDeviceToDevice);
    cudaMemcpyToSymbolAsync(clb2, d_in[14], 1 * sizeof(float),      0, cudaMemcpyDeviceToDevice);

    detect_kernel<<<1, 1>>>(ei, N);
    zero_deg_kernel<<<(N + 255) / 256, 256>>>(N);

    int eblocks = (E + 255) / 256;
    hist_kernel<<<eblocks, 256>>>(ei, E);

    int sblocks = (N + 1023) / 1024;   // 98 for N=100000
    scan_blocks_kernel<<<sblocks, 1024>>>(N);
    scan_tops_kernel<<<1, 128>>>(sblocks);
    add_offsets_kernel<<<sblocks, 1024>>>(N, E);

    scatter_kernel<<<eblocks, 256>>>(ei, ea, E);

    int cblocks = ((N * 16) + 255) / 256;
    conv1_kernel<<<cblocks, 256>>>(x, N);
    conv2_kernel<<<cblocks, 256>>>(N);

    node_mlp_kernel<<<(N + 255) / 256, 256>>>(out, N);
}

// round 6
// speedup vs baseline: 1.7319x; 1.1307x over previous
#include <cuda_runtime.h>
#include <cstdint>

#define NN   100000
#define EMAX 1600000
#define F    16

typedef unsigned long long ull;

// ---------------- scratch (static __device__, no allocs) ----------------
__device__ int g_deg[NN];
__device__ int g_cur[NN];
__device__ int g_off[NN + 1];
__device__ int g_bsum[128];
__device__ int g_dst[EMAX];
__device__ __align__(16) float g_eas[(size_t)EMAX * 8];  // sorted edge_attr
__device__ __align__(16) float g_h1[NN * F];
__device__ __align__(16) float g_h2[NN * F];
__device__ int g_idx64;

// ---------------- weights in constant memory ----------------
__constant__ __align__(16) float c1w1[16 * F];
__constant__ __align__(16) float c1b1[F];
__constant__ __align__(16) float c1w2[F * F];
__constant__ __align__(16) float c1b2[F];
__constant__ __align__(16) float c2w1[40 * F];
__constant__ __align__(16) float c2b1[F];
__constant__ __align__(16) float c2w2[F * F];
__constant__ __align__(16) float c2b2[F];
__constant__ __align__(16) float clw1[F * F];
__constant__ __align__(16) float clb1[F];
__constant__ __align__(16) float clw2[F];
__constant__ float clb2[1];

// ---------------- f32x2 packed helpers ----------------
__device__ __forceinline__ ull pk2(float a, float b) {
    ull r; asm("mov.b64 %0, {%1, %2};" : "=l"(r) : "f"(a), "f"(b)); return r;
}
__device__ __forceinline__ ull bcast2(float a) {
    ull r; asm("mov.b64 %0, {%1, %1};" : "=l"(r) : "f"(a)); return r;
}
__device__ __forceinline__ void upk2(ull v, float& a, float& b) {
    asm("mov.b64 {%0, %1}, %2;" : "=f"(a), "=f"(b) : "l"(v));
}
__device__ __forceinline__ ull fma2(ull a, ull b, ull c) {
    ull d; asm("fma.rn.f32x2 %0, %1, %2, %3;" : "=l"(d) : "l"(a), "l"(b), "l"(c)); return d;
}

// ---------------- preprocessing ----------------
__global__ void detect_kernel(const void* ei, int N) {
    const long long* p64 = (const long long*)ei;
    bool ok = true;
#pragma unroll
    for (int k = 0; k < 4; k++) {
        long long v = p64[k];
        if (v < 0 || v >= N) ok = false;
    }
    g_idx64 = ok ? 1 : 0;
}

__global__ void zero_deg_kernel(int n) {
    int i = blockIdx.x * blockDim.x + threadIdx.x;
    if (i < n) g_deg[i] = 0;
}

__global__ void hist_kernel(const void* __restrict__ ei, int E) {
    int e = blockIdx.x * blockDim.x + threadIdx.x;
    if (e >= E) return;
    int s = g_idx64 ? (int)((const long long*)ei)[e] : ((const int*)ei)[e];
    atomicAdd(&g_deg[s], 1);
}

__global__ void __launch_bounds__(1024) scan_blocks_kernel(int n) {
    __shared__ int wsum[32];
    int i = blockIdx.x * 1024 + threadIdx.x;
    int lane = threadIdx.x & 31;
    int wid  = threadIdx.x >> 5;
    int v = (i < n) ? g_deg[i] : 0;
    int s = v;
#pragma unroll
    for (int o = 1; o < 32; o <<= 1) {
        int t = __shfl_up_sync(~0u, s, o);
        if (lane >= o) s += t;
    }
    if (lane == 31) wsum[wid] = s;
    __syncthreads();
    if (wid == 0) {
        int ws = wsum[lane];
#pragma unroll
        for (int o = 1; o < 32; o <<= 1) {
            int t = __shfl_up_sync(~0u, ws, o);
            if (lane >= o) ws += t;
        }
        wsum[lane] = ws;
    }
    __syncthreads();
    int excl = s - v + (wid > 0 ? wsum[wid - 1] : 0);
    if (i < n) g_off[i] = excl;
    if (threadIdx.x == 1023) g_bsum[blockIdx.x] = wsum[31];
}

__global__ void __launch_bounds__(128) scan_tops_kernel(int nb) {
    __shared__ int wsum[4];
    int lane = threadIdx.x & 31;
    int wid  = threadIdx.x >> 5;
    int v = (threadIdx.x < nb) ? g_bsum[threadIdx.x] : 0;
    int s = v;
#pragma unroll
    for (int o = 1; o < 32; o <<= 1) {
        int t = __shfl_up_sync(~0u, s, o);
        if (lane >= o) s += t;
    }
    if (lane == 31) wsum[wid] = s;
    __syncthreads();
    int base = 0;
#pragma unroll
    for (int k = 0; k < 4; k++) if (k < wid) base += wsum[k];
    if (threadIdx.x < nb) g_bsum[threadIdx.x] = base + s - v;
}

__global__ void __launch_bounds__(1024) add_offsets_kernel(int n, int E) {
    int i = blockIdx.x * 1024 + threadIdx.x;
    if (i < n) {
        int o = g_off[i] + g_bsum[blockIdx.x];
        g_off[i] = o;
        g_cur[i] = o;
    }
    if (i == 0) g_off[n] = E;
}

__global__ void scatter_kernel(const void* __restrict__ ei,
                               const float* __restrict__ ea, int E) {
    int e = blockIdx.x * blockDim.x + threadIdx.x;
    if (e >= E) return;
    int s, d;
    if (g_idx64) {
        const long long* p = (const long long*)ei;
        s = (int)p[e]; d = (int)p[(size_t)E + e];
    } else {
        const int* p = (const int*)ei;
        s = p[e]; d = p[(size_t)E + e];
    }
    int pos = atomicAdd(&g_cur[s], 1);
    g_dst[pos] = d;
    float4 a0 = *(const float4*)(ea + (size_t)e * 8);
    float4 a1 = *(const float4*)(ea + (size_t)e * 8 + 4);
    *(float4*)(g_eas + (size_t)pos * 8)     = a0;
    *(float4*)(g_eas + (size_t)pos * 8 + 4) = a1;
}

// ---------------- conv layers: half-warp per node, f32x2 packed MLP ----------------
__global__ void __launch_bounds__(256) conv1_kernel(const float* __restrict__ x, int N) {
    int gid = blockIdx.x * blockDim.x + threadIdx.x;
    int node = gid >> 4;
    int l = gid & 15;
    if (node >= N) return;

    int start = g_off[node];
    int end   = g_off[node + 1];

    const ull* w1p = reinterpret_cast<const ull*>(c1w1);  // [16][8] pairs
    const ull* w2p = reinterpret_cast<const ull*>(c1w2);  // [16][8] pairs

    float4 xi = *(const float4*)(x + (size_t)node * 4);

    // Hbase = b1 + xi-part of layer 1 (rows 0..3), packed over j
    ull Hb[8];
#pragma unroll
    for (int k = 0; k < 8; k++) Hb[k] = pk2(c1b1[2*k], c1b1[2*k+1]);
    {
        float xv[4] = {xi.x, xi.y, xi.z, xi.w};
#pragma unroll
        for (int i = 0; i < 4; i++) {
            ull vv = bcast2(xv[i]);
#pragma unroll
            for (int k = 0; k < 8; k++) Hb[k] = fma2(vv, w1p[i*8 + k], Hb[k]);
        }
    }

    float acc[F];
#pragma unroll
    for (int j = 0; j < F; j++) acc[j] = 0.f;

    for (int p = start + l; p < end; p += 16) {
        int d = g_dst[p];
        float4 xj = *(const float4*)(x + (size_t)d * 4);
        float4 a0 = *(const float4*)(g_eas + (size_t)p * 8);
        float4 a1 = *(const float4*)(g_eas + (size_t)p * 8 + 4);
        float in[12] = {xj.x, xj.y, xj.z, xj.w,
                        a0.x, a0.y, a0.z, a0.w, a1.x, a1.y, a1.z, a1.w};

        ull H[8];
#pragma unroll
        for (int k = 0; k < 8; k++) H[k] = Hb[k];
#pragma unroll
        for (int i = 0; i < 12; i++) {
            ull vv = bcast2(in[i]);
#pragma unroll
            for (int k = 0; k < 8; k++) H[k] = fma2(vv, w1p[(4+i)*8 + k], H[k]);
        }

        ull O[8];
#pragma unroll
        for (int k = 0; k < 8; k++) O[k] = pk2(c1b2[2*k], c1b2[2*k+1]);
#pragma unroll
        for (int k = 0; k < 8; k++) {
            float a, b; upk2(H[k], a, b);
            a = fmaxf(a, 0.f); b = fmaxf(b, 0.f);
            ull va = bcast2(a), vb = bcast2(b);
#pragma unroll
            for (int m = 0; m < 8; m++) O[m] = fma2(va, w2p[(2*k)*8 + m], O[m]);
#pragma unroll
            for (int m = 0; m < 8; m++) O[m] = fma2(vb, w2p[(2*k+1)*8 + m], O[m]);
        }
#pragma unroll
        for (int m = 0; m < 8; m++) {
            float a, b; upk2(O[m], a, b);
            acc[2*m]   = fmaxf(acc[2*m],   a);
            acc[2*m+1] = fmaxf(acc[2*m+1], b);
        }
    }

    unsigned mask = 0xFFFFu << (threadIdx.x & 16);
#pragma unroll
    for (int w = 8; w >= 1; w >>= 1) {
#pragma unroll
        for (int j = 0; j < F; j++)
            acc[j] = fmaxf(acc[j], __shfl_xor_sync(mask, acc[j], w, 16));
    }
    if (l == 0) {
        float* out = g_h1 + (size_t)node * F;
#pragma unroll
        for (int q = 0; q < 4; q++)
            *(float4*)(out + q * 4) = make_float4(acc[q*4], acc[q*4+1], acc[q*4+2], acc[q*4+3]);
    }
}

__global__ void __launch_bounds__(256) conv2_kernel(int N) {
    int gid = blockIdx.x * blockDim.x + threadIdx.x;
    int node = gid >> 4;
    int l = gid & 15;
    if (node >= N) return;

    int start = g_off[node];
    int end   = g_off[node + 1];

    const ull* w1p = reinterpret_cast<const ull*>(c2w1);  // [40][8] pairs
    const ull* w2p = reinterpret_cast<const ull*>(c2w2);  // [16][8] pairs

    // Hbase = b1 + hi-part of layer 1 (rows 0..15), packed over j
    ull Hb[8];
#pragma unroll
    for (int k = 0; k < 8; k++) Hb[k] = pk2(c2b1[2*k], c2b1[2*k+1]);
    {
        const float4* ph = (const float4*)(g_h1 + (size_t)node * F);
#pragma unroll
        for (int q = 0; q < 4; q++) {
            float4 v = ph[q];
            float hv[4] = {v.x, v.y, v.z, v.w};
#pragma unroll
            for (int r = 0; r < 4; r++) {
                ull vv = bcast2(hv[r]);
                int i = q * 4 + r;
#pragma unroll
                for (int k = 0; k < 8; k++) Hb[k] = fma2(vv, w1p[i*8 + k], Hb[k]);
            }
        }
    }

    float acc[F];
#pragma unroll
    for (int j = 0; j < F; j++) acc[j] = 0.f;

    for (int p = start + l; p < end; p += 16) {
        int d = g_dst[p];
        float in[24];
        {
            const float4* pd = (const float4*)(g_h1 + (size_t)d * F);
#pragma unroll
            for (int q = 0; q < 4; q++) {
                float4 v = pd[q];
                in[q*4+0] = v.x; in[q*4+1] = v.y; in[q*4+2] = v.z; in[q*4+3] = v.w;
            }
            float4 a0 = *(const float4*)(g_eas + (size_t)p * 8);
            float4 a1 = *(const float4*)(g_eas + (size_t)p * 8 + 4);
            in[16] = a0.x; in[17] = a0.y; in[18] = a0.z; in[19] = a0.w;
            in[20] = a1.x; in[21] = a1.y; in[22] = a1.z; in[23] = a1.w;
        }

        ull H[8];
#pragma unroll
        for (int k = 0; k < 8; k++) H[k] = Hb[k];
#pragma unroll
        for (int i = 0; i < 24; i++) {
            ull vv = bcast2(in[i]);
#pragma unroll
            for (int k = 0; k < 8; k++) H[k] = fma2(vv, w1p[(16+i)*8 + k], H[k]);
        }

        ull O[8];
#pragma unroll
        for (int k = 0; k < 8; k++) O[k] = pk2(c2b2[2*k], c2b2[2*k+1]);
#pragma unroll
        for (int k = 0; k < 8; k++) {
            float a, b; upk2(H[k], a, b);
            a = fmaxf(a, 0.f); b = fmaxf(b, 0.f);
            ull va = bcast2(a), vb = bcast2(b);
#pragma unroll
            for (int m = 0; m < 8; m++) O[m] = fma2(va, w2p[(2*k)*8 + m], O[m]);
#pragma unroll
            for (int m = 0; m < 8; m++) O[m] = fma2(vb, w2p[(2*k+1)*8 + m], O[m]);
        }
#pragma unroll
        for (int m = 0; m < 8; m++) {
            float a, b; upk2(O[m], a, b);
            acc[2*m]   = fmaxf(acc[2*m],   a);
            acc[2*m+1] = fmaxf(acc[2*m+1], b);
        }
    }

    unsigned mask = 0xFFFFu << (threadIdx.x & 16);
#pragma unroll
    for (int w = 8; w >= 1; w >>= 1) {
#pragma unroll
        for (int j = 0; j < F; j++)
            acc[j] = fmaxf(acc[j], __shfl_xor_sync(mask, acc[j], w, 16));
    }
    if (l == 0) {
        float* out = g_h2 + (size_t)node * F;
#pragma unroll
        for (int q = 0; q < 4; q++)
            *(float4*)(out + q * 4) = make_float4(acc[q*4], acc[q*4+1], acc[q*4+2], acc[q*4+3]);
    }
}

// ---------------- final node MLP (packed) ----------------
__global__ void __launch_bounds__(256) node_mlp_kernel(float* __restrict__ out, int n) {
    int i = blockIdx.x * blockDim.x + threadIdx.x;
    if (i >= n) return;

    const ull* w1p = reinterpret_cast<const ull*>(clw1);  // [16][8]

    ull H[8];
#pragma unroll
    for (int k = 0; k < 8; k++) H[k] = pk2(clb1[2*k], clb1[2*k+1]);

    const float4* ph = (const float4*)(g_h2 + (size_t)i * F);
#pragma unroll
    for (int q = 0; q < 4; q++) {
        float4 v = ph[q];
        float hv[4] = {v.x, v.y, v.z, v.w};
#pragma unroll
        for (int r = 0; r < 4; r++) {
            ull vv = bcast2(hv[r]);
            int kk = q * 4 + r;
#pragma unroll
            for (int k = 0; k < 8; k++) H[k] = fma2(vv, w1p[kk*8 + k], H[k]);
        }
    }

    float acc = clb2[0];
#pragma unroll
    for (int k = 0; k < 8; k++) {
        float a, b; upk2(H[k], a, b);
        acc += fmaxf(a, 0.f) * clw2[2*k] + fmaxf(b, 0.f) * clw2[2*k+1];
    }
    out[i] = acc;
}

// ---------------- launch ----------------
extern "C" void kernel_launch(void* const* d_in, const int* in_sizes, int n_in,
                              void* d_out, int out_size)
{
    const float* x  = (const float*)d_in[0];
    const void*  ei = d_in[1];
    const float* ea = (const float*)d_in[2];

    int N = in_sizes[0] / 4;   // x is [N,4]
    int E = in_sizes[2] / 8;   // edge_attr is [E,8]
    float* out = (float*)d_out;

    cudaMemcpyToSymbolAsync(c1w1, d_in[3],  16 * F * sizeof(float), 0, cudaMemcpyDeviceToDevice);
    cudaMemcpyToSymbolAsync(c1b1, d_in[4],  F * sizeof(float),      0, cudaMemcpyDeviceToDevice);
    cudaMemcpyToSymbolAsync(c1w2, d_in[5],  F * F * sizeof(float),  0, cudaMemcpyDeviceToDevice);
    cudaMemcpyToSymbolAsync(c1b2, d_in[6],  F * sizeof(float),      0, cudaMemcpyDeviceToDevice);
    cudaMemcpyToSymbolAsync(c2w1, d_in[7],  40 * F * sizeof(float), 0, cudaMemcpyDeviceToDevice);
    cudaMemcpyToSymbolAsync(c2b1, d_in[8],  F * sizeof(float),      0, cudaMemcpyDeviceToDevice);
    cudaMemcpyToSymbolAsync(c2w2, d_in[9],  F * F * sizeof(float),  0, cudaMemcpyDeviceToDevice);
    cudaMemcpyToSymbolAsync(c2b2, d_in[10], F * sizeof(float),      0, cudaMemcpyDeviceToDevice);
    cudaMemcpyToSymbolAsync(clw1, d_in[11], F * F * sizeof(float),  0, cudaMemcpyDeviceToDevice);
    cudaMemcpyToSymbolAsync(clb1, d_in[12], F * sizeof(float),      0, cudaMemcpyDeviceToDevice);
    cudaMemcpyToSymbolAsync(clw2, d_in[13], F * sizeof(float),      0, cudaMemcpyDeviceToDevice);
    cudaMemcpyToSymbolAsync(clb2, d_in[14], 1 * sizeof(float),      0, cudaMemcpyDeviceToDevice);

    detect_kernel<<<1, 1>>>(ei, N);
    zero_deg_kernel<<<(N + 255) / 256, 256>>>(N);

    int eblocks = (E + 255) / 256;
    hist_kernel<<<eblocks, 256>>>(ei, E);

    int sblocks = (N + 1023) / 1024;
    scan_blocks_kernel<<<sblocks, 1024>>>(N);
    scan_tops_kernel<<<1, 128>>>(sblocks);
    add_offsets_kernel<<<sblocks, 1024>>>(N, E);

    scatter_kernel<<<eblocks, 256>>>(ei, ea, E);

    int cblocks = ((N * 16) + 255) / 256;
    conv1_kernel<<<cblocks, 256>>>(x, N);
    conv2_kernel<<<cblocks, 256>>>(N);

    node_mlp_kernel<<<(N + 255) / 256, 256>>>(out, N);
}